// round 15
// baseline (speedup 1.0000x reference)
#include <cuda_runtime.h>
#include <cuda_fp16.h>

#define TCAP  200
#define MDIM  256
#define BMAX  8192

__device__ float g_W[(size_t)BMAX * MDIM];   // 8 MB scratch

typedef unsigned long long ull;

// ---- packed fp32x2 helpers ----
__device__ __forceinline__ ull fma2(ull a, ull b, ull c) {
    ull d;
    asm("fma.rn.f32x2 %0, %1, %2, %3;" : "=l"(d) : "l"(a), "l"(b), "l"(c));
    return d;
}
__device__ __forceinline__ ull add2(ull a, ull b) {
    ull d;
    asm("add.rn.f32x2 %0, %1, %2;" : "=l"(d) : "l"(a), "l"(b));
    return d;
}
__device__ __forceinline__ ull pack2(float x, float y) {
    ull r;
    asm("mov.b64 %0, {%1, %2};" : "=l"(r) : "f"(x), "f"(y));
    return r;
}
__device__ __forceinline__ float2 unpack2(ull a) {
    float2 f;
    asm("mov.b64 {%0, %1}, %2;" : "=f"(f.x), "=f"(f.y) : "l"(a));
    return f;
}
__device__ __forceinline__ ull h2f2(unsigned h) {
    ull r;
    asm("{\n\t.reg .b16 lo, hi;\n\t.reg .f32 flo, fhi;\n\t"
        "mov.b32 {lo, hi}, %1;\n\t"
        "cvt.f32.f16 flo, lo;\n\tcvt.f32.f16 fhi, hi;\n\t"
        "mov.b64 %0, {flo, fhi};\n\t}" : "=l"(r) : "r"(h));
    return r;
}

// ---------------------------------------------------------------------------
// K1 (fast, PDL trigger): 32 batches/CTA, 256 CTAs (~half the serial chain of
// the 64-batch version; still a single wave at 4 CTAs/SM).
// ---------------------------------------------------------------------------
__global__ __launch_bounds__(256) void k1_w(const float* __restrict__ query,
                                            const float* __restrict__ Qm,
                                            const float* __restrict__ Km, int B) {
    cudaTriggerProgrammaticLaunchCompletion();

    __shared__ float sQ[64 * 64];
    __shared__ float sK[64 * 68];
    __shared__ float qs[32 * 64];
    __shared__ float qp[32 * 64];
    int b0 = blockIdx.x * 32, t = threadIdx.x;

    for (int idx = t; idx < 4096; idx += 256) {
        sQ[idx] = Qm[idx];
        sK[(idx >> 6) * 68 + (idx & 63)] = Km[idx];
    }
    for (int idx = t; idx < 2048; idx += 256) {
        int bb = idx >> 6;
        qs[idx] = (b0 + bb < B) ? query[(size_t)(b0 + bb) * 64 + (idx & 63)] : 0.f;
    }
    __syncthreads();

    // qp: bg = t>>6 handles 8 batches, c = t&63
    {
        int bg = t >> 6, c = t & 63;
        float acc[8];
#pragma unroll
        for (int b = 0; b < 8; b++) acc[b] = 0.f;
#pragma unroll 4
        for (int i4 = 0; i4 < 16; i4++) {
            float q0 = sQ[(i4 * 4 + 0) * 64 + c];
            float q1 = sQ[(i4 * 4 + 1) * 64 + c];
            float q2 = sQ[(i4 * 4 + 2) * 64 + c];
            float q3 = sQ[(i4 * 4 + 3) * 64 + c];
#pragma unroll
            for (int b = 0; b < 8; b++) {
                float4 v = *(const float4*)(qs + (bg * 8 + b) * 64 + i4 * 4);
                acc[b] += v.x * q0 + v.y * q1 + v.z * q2 + v.w * q3;
            }
        }
#pragma unroll
        for (int b = 0; b < 8; b++)
            qp[(bg * 8 + b) * 64 + c] = acc[b];
    }
    __syncthreads();

    {
        int h = t >> 6, a = t & 63;
        const float4* K4 = (const float4*)(sK + a * 68 + h * 16);
        float4 k0 = K4[0], k1 = K4[1], k2 = K4[2], k3 = K4[3];
        int bmax = B - b0; if (bmax > 32) bmax = 32;
        for (int b = 0; b < bmax; b++) {
            const float4* q4 = (const float4*)(qp + b * 64 + h * 16);
            float4 qa = q4[0], qb = q4[1], qc = q4[2], qd = q4[3];
            float wv = qa.x * k0.x + qa.y * k0.y + qa.z * k0.z + qa.w * k0.w
                     + qb.x * k1.x + qb.y * k1.y + qb.z * k1.z + qb.w * k1.w
                     + qc.x * k2.x + qc.y * k2.y + qc.z * k2.z + qc.w * k2.w
                     + qd.x * k3.x + qd.y * k3.y + qd.z * k3.z + qd.w * k3.w;
            g_W[(size_t)(b0 + b) * MDIM + t] = 0.125f * wv;
        }
    }
}

// ---------------------------------------------------------------------------
// K2: R14 attention (fused softmax, fp16 p) + widened Phase F.
// ---------------------------------------------------------------------------
#define SA_BYTES   (TCAP * 128)               // 25600: fp16 swizzled tile (aliased later)
#define SW_OFF     SA_BYTES                   // 1024: W row, later ctx
#define PH_OFF     (SW_OFF + 1024)            // 1600: p as half2[2][200]
#define RED_OFF    (PH_OFF + 1600)            // 128: redmax[16] + redsum[16]
#define SINV_OFF   (RED_OFF + 128)            // 16
#define SMEM_BYTES (SINV_OFF + 16)            // 28368

extern __shared__ char s_raw[];

__global__ __launch_bounds__(128, 8) void k2_fused(const float* __restrict__ act,
                                                   const float* __restrict__ V,
                                                   float* __restrict__ out, int nsk) {
    char*    sab   = s_raw;
    float*   sw    = (float*)(s_raw + SW_OFF);
    __half2* ph0   = (__half2*)(s_raw + PH_OFF);
    __half2* ph1   = (__half2*)(s_raw + PH_OFF + 800);
    float*   redm  = (float*)(s_raw + RED_OFF);
    float*   reds  = (float*)(s_raw + RED_OFF + 64);
    float*   sinv  = (float*)(s_raw + SINV_OFF);
    float*   partf = (float*)s_raw;           // aliases tile after ctx phase

    int b = blockIdx.x;
    int t = threadIdx.x;
    int wid = t >> 5, lane = t & 31;

    // ---- Phase A: action tile -> fp16, XOR-swizzled (pure DRAM; overlaps k1)
    {
        const float4* ga = (const float4*)(act + (size_t)b * nsk * 64);
        int ngroups = nsk * 8;
#pragma unroll 2
        for (int g = t; g < ngroups; g += 128) {
            float4 fa = ga[2 * g];
            float4 fb = ga[2 * g + 1];
            __half2 h0 = __floats2half2_rn(fa.x, fa.y);
            __half2 h1 = __floats2half2_rn(fa.z, fa.w);
            __half2 h2 = __floats2half2_rn(fb.x, fb.y);
            __half2 h3 = __floats2half2_rn(fb.z, fb.w);
            uint4 pk;
            pk.x = *(const unsigned*)&h0;
            pk.y = *(const unsigned*)&h1;
            pk.z = *(const unsigned*)&h2;
            pk.w = *(const unsigned*)&h3;
            unsigned off = ((unsigned)g << 4) ^ ((((unsigned)g >> 3) & 7u) << 4);
            *(uint4*)(sab + off) = pk;
        }
    }

    // ---- Wait for k1 (g_W), then load W row
    cudaGridDependencySynchronize();
    sw[t]       = g_W[(size_t)b * MDIM + t];
    sw[t + 128] = g_W[(size_t)b * MDIM + t + 128];
    __syncthreads();

    // ---- Phase B+C fused: scores in regs, block softmax, p stored fp16
    {
        int sk1 = t, sk2 = t + 128;
        bool v1 = sk1 < nsk, v2 = sk2 < nsk;
        float s1[4] = {-1e30f, -1e30f, -1e30f, -1e30f};
        float s2[4] = {-1e30f, -1e30f, -1e30f, -1e30f};
        if (v1) {
            unsigned swb1 = (unsigned)(sk1 * 128) | (((unsigned)sk1 & 7u) << 4);
            unsigned swb2 = (unsigned)(sk2 * 128) | (((unsigned)sk2 & 7u) << 4);
            ull a1[4] = {0, 0, 0, 0}, a2[4] = {0, 0, 0, 0};
#pragma unroll
            for (int i = 0; i < 8; i++) {
                uint4 av1 = *(const uint4*)(sab + (swb1 ^ ((unsigned)i << 4)));
                uint4 av2 = make_uint4(0, 0, 0, 0);
                if (v2) av2 = *(const uint4*)(sab + (swb2 ^ ((unsigned)i << 4)));
                ull d1[4] = {h2f2(av1.x), h2f2(av1.y), h2f2(av1.z), h2f2(av1.w)};
                ull d2[4] = {h2f2(av2.x), h2f2(av2.y), h2f2(av2.z), h2f2(av2.w)};
#pragma unroll
                for (int h = 0; h < 4; h++) {
                    ulonglong2 wA = *(const ulonglong2*)(sw + h * 64 + i * 8);
                    ulonglong2 wB = *(const ulonglong2*)(sw + h * 64 + i * 8 + 4);
                    a1[h] = fma2(d1[0], wA.x, a1[h]);
                    a1[h] = fma2(d1[1], wA.y, a1[h]);
                    a1[h] = fma2(d1[2], wB.x, a1[h]);
                    a1[h] = fma2(d1[3], wB.y, a1[h]);
                    a2[h] = fma2(d2[0], wA.x, a2[h]);
                    a2[h] = fma2(d2[1], wA.y, a2[h]);
                    a2[h] = fma2(d2[2], wB.x, a2[h]);
                    a2[h] = fma2(d2[3], wB.y, a2[h]);
                }
            }
#pragma unroll
            for (int h = 0; h < 4; h++) {
                float2 f1 = unpack2(a1[h]); s1[h] = f1.x + f1.y;
                if (v2) { float2 f2 = unpack2(a2[h]); s2[h] = f2.x + f2.y; }
            }
        }

        // block max per head
        float mx[4];
#pragma unroll
        for (int h = 0; h < 4; h++) mx[h] = fmaxf(s1[h], s2[h]);
#pragma unroll
        for (int o = 16; o; o >>= 1)
#pragma unroll
            for (int h = 0; h < 4; h++)
                mx[h] = fmaxf(mx[h], __shfl_xor_sync(0xffffffffu, mx[h], o));
        if (lane == 0) {
#pragma unroll
            for (int h = 0; h < 4; h++) redm[wid * 4 + h] = mx[h];
        }
        __syncthreads();
        float mm[4];
#pragma unroll
        for (int h = 0; h < 4; h++)
            mm[h] = fmaxf(fmaxf(redm[h], redm[4 + h]),
                          fmaxf(redm[8 + h], redm[12 + h]));

        // p = exp(s - m), block sum per head, store p fp16
        float p1[4], p2[4], sm[4];
#pragma unroll
        for (int h = 0; h < 4; h++) {
            p1[h] = v1 ? __expf(s1[h] - mm[h]) : 0.f;
            p2[h] = v2 ? __expf(s2[h] - mm[h]) : 0.f;
            sm[h] = p1[h] + p2[h];
        }
#pragma unroll
        for (int o = 16; o; o >>= 1)
#pragma unroll
            for (int h = 0; h < 4; h++)
                sm[h] += __shfl_xor_sync(0xffffffffu, sm[h], o);
        if (lane == 0) {
#pragma unroll
            for (int h = 0; h < 4; h++) reds[wid * 4 + h] = sm[h];
        }
        if (v1) {
            ph0[sk1] = __floats2half2_rn(p1[0], p1[1]);
            ph1[sk1] = __floats2half2_rn(p1[2], p1[3]);
        }
        if (v2) {
            ph0[sk2] = __floats2half2_rn(p2[0], p2[1]);
            ph1[sk2] = __floats2half2_rn(p2[2], p2[3]);
        }
    }
    __syncthreads();

    if (t < 4) {
        float s = reds[t] + reds[4 + t] + reds[8 + t] + reds[12 + t];
        sinv[t] = 1.f / s;
    }

    // ---- Phase D: ctx partials. 128 threads = 16 sk-groups x 8 dim-octets.
    ull acc[16];
    {
        int sg = t >> 3, c8 = t & 7;
#pragma unroll
        for (int v = 0; v < 16; v++) acc[v] = 0ull;
        int chunk = (nsk + 15) >> 4;
        int sk0 = sg * chunk;
        int sk1e = sk0 + chunk; if (sk1e > nsk) sk1e = nsk;
        for (int sk = sk0; sk < sk1e; sk++) {
            unsigned off = (unsigned)(sk * 128) |
                           ((((unsigned)sk & 7u) ^ (unsigned)c8) << 4);
            uint4 av = *(const uint4*)(sab + off);
            ull d0 = h2f2(av.x), d1 = h2f2(av.y), d2 = h2f2(av.z), d3 = h2f2(av.w);
            float2 p01 = __half22float2(ph0[sk]);
            float2 p23 = __half22float2(ph1[sk]);
            ull ph0p = pack2(p01.x, p01.x), ph1p = pack2(p01.y, p01.y);
            ull ph2p = pack2(p23.x, p23.x), ph3p = pack2(p23.y, p23.y);
            acc[0]  = fma2(ph0p, d0, acc[0]);  acc[1]  = fma2(ph0p, d1, acc[1]);
            acc[2]  = fma2(ph0p, d2, acc[2]);  acc[3]  = fma2(ph0p, d3, acc[3]);
            acc[4]  = fma2(ph1p, d0, acc[4]);  acc[5]  = fma2(ph1p, d1, acc[5]);
            acc[6]  = fma2(ph1p, d2, acc[6]);  acc[7]  = fma2(ph1p, d3, acc[7]);
            acc[8]  = fma2(ph2p, d0, acc[8]);  acc[9]  = fma2(ph2p, d1, acc[9]);
            acc[10] = fma2(ph2p, d2, acc[10]); acc[11] = fma2(ph2p, d3, acc[11]);
            acc[12] = fma2(ph3p, d0, acc[12]); acc[13] = fma2(ph3p, d1, acc[13]);
            acc[14] = fma2(ph3p, d2, acc[14]); acc[15] = fma2(ph3p, d3, acc[15]);
        }
#pragma unroll
        for (int v = 0; v < 16; v++) {
            acc[v] = add2(acc[v], __shfl_xor_sync(0xffffffffu, acc[v], 8));
            acc[v] = add2(acc[v], __shfl_xor_sync(0xffffffffu, acc[v], 16));
        }
    }
    __syncthreads();   // tile reads complete; alias partials over tile

    if ((t & 24) == 0) {
        int w = t >> 5, c8 = t & 7;
        ull* pw = (ull*)partf + w * 128 + c8 * 4;
#pragma unroll
        for (int h = 0; h < 4; h++)
#pragma unroll
            for (int p = 0; p < 4; p++)
                pw[h * 32 + p] = acc[h * 4 + p];
    }
    __syncthreads();

    // ---- Phase E: combine partials -> normalized ctx into sw
    {
        float r0 = partf[t]       + partf[256 + t]       + partf[512 + t]       + partf[768 + t];
        float r1 = partf[t + 128] + partf[256 + t + 128] + partf[512 + t + 128] + partf[768 + t + 128];
        sw[t]       = r0 * sinv[t >> 6];
        sw[t + 128] = r1 * sinv[(t + 128) >> 6];
    }
    __syncthreads();

    // ---- Phase F (widened): all 128 threads; thread (ar = t>>6, c = t&63)
    //      covers a-range [ar*32, ar*32+32)
    {
        int ar = t >> 6, c = t & 63;
        int h = c >> 4;
        const ull* cx = (const ull*)(sw + h * 64 + ar * 32);
        ull acc2 = 0ull;
#pragma unroll
        for (int a = 0; a < 16; a++) {
            float v0 = __ldg(V + (size_t)(ar * 32 + 2 * a) * 64 + c);
            float v1 = __ldg(V + (size_t)(ar * 32 + 2 * a + 1) * 64 + c);
            acc2 = fma2(cx[a], pack2(v0, v1), acc2);
        }
        float2 f = unpack2(acc2);
        partf[ar * 68 + c] = f.x + f.y;
    }
    __syncthreads();

    if (t < 64)
        out[(size_t)b * 64 + t] = partf[t] + partf[68 + t];
}

// ---------------------------------------------------------------------------
extern "C" void kernel_launch(void* const* d_in, const int* in_sizes, int n_in,
                              void* d_out, int out_size) {
    const float* query = (const float*)d_in[0];   // [B,1,64]
    const float* act   = (const float*)d_in[1];   // [B,SK,64]
    const float* Q     = (const float*)d_in[2];   // [64,64]
    const float* K     = (const float*)d_in[3];   // [64,64]
    const float* V     = (const float*)d_in[4];   // [64,64]
    float* out = (float*)d_out;

    int B   = in_sizes[0] / 64;
    int nsk = in_sizes[1] / (B * 64);
    if (nsk > TCAP) nsk = TCAP;

    cudaFuncSetAttribute(k2_fused, cudaFuncAttributeMaxDynamicSharedMemorySize, SMEM_BYTES);

    k1_w<<<(B + 31) / 32, 256>>>(query, Q, K, B);

    cudaLaunchConfig_t cfg = {};
    cfg.gridDim = dim3((unsigned)B, 1, 1);
    cfg.blockDim = dim3(128, 1, 1);
    cfg.dynamicSmemBytes = SMEM_BYTES;
    cfg.stream = 0;
    cudaLaunchAttribute attrs[1];
    attrs[0].id = cudaLaunchAttributeProgrammaticStreamSerialization;
    attrs[0].val.programmaticStreamSerializationAllowed = 1;
    cfg.attrs = attrs;
    cfg.numAttrs = 1;
    cudaLaunchKernelEx(&cfg, k2_fused, act, V, out, nsk);
}

// round 16
// speedup vs baseline: 1.0348x; 1.0348x over previous
#include <cuda_runtime.h>
#include <cuda_fp16.h>

#define TCAP  200
#define MDIM  256
#define BMAX  8192

__device__ float g_W[(size_t)BMAX * MDIM];   // 8 MB scratch

typedef unsigned long long ull;

// ---- packed fp32x2 helpers ----
__device__ __forceinline__ ull fma2(ull a, ull b, ull c) {
    ull d;
    asm("fma.rn.f32x2 %0, %1, %2, %3;" : "=l"(d) : "l"(a), "l"(b), "l"(c));
    return d;
}
__device__ __forceinline__ ull add2(ull a, ull b) {
    ull d;
    asm("add.rn.f32x2 %0, %1, %2;" : "=l"(d) : "l"(a), "l"(b));
    return d;
}
__device__ __forceinline__ ull pack2(float x, float y) {
    ull r;
    asm("mov.b64 %0, {%1, %2};" : "=l"(r) : "f"(x), "f"(y));
    return r;
}
__device__ __forceinline__ float2 unpack2(ull a) {
    float2 f;
    asm("mov.b64 {%0, %1}, %2;" : "=f"(f.x), "=f"(f.y) : "l"(a));
    return f;
}
__device__ __forceinline__ ull h2f2(unsigned h) {
    ull r;
    asm("{\n\t.reg .b16 lo, hi;\n\t.reg .f32 flo, fhi;\n\t"
        "mov.b32 {lo, hi}, %1;\n\t"
        "cvt.f32.f16 flo, lo;\n\tcvt.f32.f16 fhi, hi;\n\t"
        "mov.b64 %0, {flo, fhi};\n\t}" : "=l"(r) : "r"(h));
    return r;
}

// ---------------------------------------------------------------------------
// K1 (fat, PDL trigger): 64 batches/CTA, 128 CTAs — the R14/R12 version.
// ---------------------------------------------------------------------------
__global__ __launch_bounds__(256) void k1_w(const float* __restrict__ query,
                                            const float* __restrict__ Qm,
                                            const float* __restrict__ Km, int B) {
    cudaTriggerProgrammaticLaunchCompletion();

    __shared__ float sQ[64 * 64];
    __shared__ float qs[64 * 64];
    __shared__ float sK[64 * 68];
    __shared__ float qp[64 * 64];
    int b0 = blockIdx.x * 64, t = threadIdx.x;

    for (int idx = t; idx < 4096; idx += 256) {
        sQ[idx] = Qm[idx];
        sK[(idx >> 6) * 68 + (idx & 63)] = Km[idx];
        int bb = idx >> 6;
        qs[idx] = (b0 + bb < B) ? query[(size_t)(b0 + bb) * 64 + (idx & 63)] : 0.f;
    }
    __syncthreads();

    {
        int bg = t >> 6, c = t & 63;
        float acc[16];
#pragma unroll
        for (int b = 0; b < 16; b++) acc[b] = 0.f;
#pragma unroll 4
        for (int i4 = 0; i4 < 16; i4++) {
            float q0 = sQ[(i4 * 4 + 0) * 64 + c];
            float q1 = sQ[(i4 * 4 + 1) * 64 + c];
            float q2 = sQ[(i4 * 4 + 2) * 64 + c];
            float q3 = sQ[(i4 * 4 + 3) * 64 + c];
#pragma unroll
            for (int b = 0; b < 16; b++) {
                float4 v = *(const float4*)(qs + (bg * 16 + b) * 64 + i4 * 4);
                acc[b] += v.x * q0 + v.y * q1 + v.z * q2 + v.w * q3;
            }
        }
#pragma unroll
        for (int b = 0; b < 16; b++)
            qp[(bg * 16 + b) * 64 + c] = acc[b];
    }
    __syncthreads();

    {
        int h = t >> 6, a = t & 63;
        const float4* K4 = (const float4*)(sK + a * 68 + h * 16);
        float4 k0 = K4[0], k1 = K4[1], k2 = K4[2], k3 = K4[3];
        int bmax = B - b0; if (bmax > 64) bmax = 64;
        for (int b = 0; b < bmax; b++) {
            const float4* q4 = (const float4*)(qp + b * 64 + h * 16);
            float4 qa = q4[0], qb = q4[1], qc = q4[2], qd = q4[3];
            float wv = qa.x * k0.x + qa.y * k0.y + qa.z * k0.z + qa.w * k0.w
                     + qb.x * k1.x + qb.y * k1.y + qb.z * k1.z + qb.w * k1.w
                     + qc.x * k2.x + qc.y * k2.y + qc.z * k2.z + qc.w * k2.w
                     + qd.x * k3.x + qd.y * k3.y + qd.z * k3.z + qd.w * k3.w;
            g_W[(size_t)(b0 + b) * MDIM + t] = 0.125f * wv;
        }
    }
}

// ---------------------------------------------------------------------------
// K2: R14 attention (fused softmax, fp16 p) with COALESCED phase-A loads.
// ---------------------------------------------------------------------------
#define SA_BYTES   (TCAP * 128)               // 25600: fp16 swizzled tile (aliased later)
#define SW_OFF     SA_BYTES                   // 1024: W row, later ctx
#define PH_OFF     (SW_OFF + 1024)            // 1600: p as half2[2][200]
#define RED_OFF    (PH_OFF + 1600)            // 128: redmax[16] + redsum[16]
#define SINV_OFF   (RED_OFF + 128)            // 16
#define SMEM_BYTES (SINV_OFF + 16)            // 28368

extern __shared__ char s_raw[];

__global__ __launch_bounds__(128, 8) void k2_fused(const float* __restrict__ act,
                                                   const float* __restrict__ V,
                                                   float* __restrict__ out, int nsk) {
    char*    sab   = s_raw;
    float*   sw    = (float*)(s_raw + SW_OFF);
    __half2* ph0   = (__half2*)(s_raw + PH_OFF);
    __half2* ph1   = (__half2*)(s_raw + PH_OFF + 800);
    float*   redm  = (float*)(s_raw + RED_OFF);
    float*   reds  = (float*)(s_raw + RED_OFF + 64);
    float*   sinv  = (float*)(s_raw + SINV_OFF);
    float*   partf = (float*)s_raw;           // aliases tile after ctx phase

    int b = blockIdx.x;
    int t = threadIdx.x;
    int wid = t >> 5, lane = t & 31;

    // ---- Phase A: action tile -> fp16, XOR-swizzled.
    //      COALESCED: thread j loads consecutive float4s (4 lines/warp-instr),
    //      stores 8B uint2 at slot (g = j>>1, half hs = j&1).
    {
        const float4* ga = (const float4*)(act + (size_t)b * nsk * 64);
        int nq = nsk * 16;                    // float4 count (3200)
#pragma unroll 4
        for (int j = t; j < nq; j += 128) {
            float4 f = ga[j];
            __half2 h0 = __floats2half2_rn(f.x, f.y);
            __half2 h1 = __floats2half2_rn(f.z, f.w);
            uint2 pk;
            pk.x = *(const unsigned*)&h0;
            pk.y = *(const unsigned*)&h1;
            unsigned g = (unsigned)j >> 1, hs = (unsigned)j & 1u;
            unsigned off = ((g << 4) ^ (((g >> 3) & 7u) << 4)) + (hs << 3);
            *(uint2*)(sab + off) = pk;
        }
    }

    // ---- Wait for k1 (g_W), then load W row
    cudaGridDependencySynchronize();
    sw[t]       = g_W[(size_t)b * MDIM + t];
    sw[t + 128] = g_W[(size_t)b * MDIM + t + 128];
    __syncthreads();

    // ---- Phase B+C fused: scores in regs, block softmax, p stored fp16
    {
        int sk1 = t, sk2 = t + 128;
        bool v1 = sk1 < nsk, v2 = sk2 < nsk;
        float s1[4] = {-1e30f, -1e30f, -1e30f, -1e30f};
        float s2[4] = {-1e30f, -1e30f, -1e30f, -1e30f};
        if (v1) {
            unsigned swb1 = (unsigned)(sk1 * 128) | (((unsigned)sk1 & 7u) << 4);
            unsigned swb2 = (unsigned)(sk2 * 128) | (((unsigned)sk2 & 7u) << 4);
            ull a1[4] = {0, 0, 0, 0}, a2[4] = {0, 0, 0, 0};
#pragma unroll
            for (int i = 0; i < 8; i++) {
                uint4 av1 = *(const uint4*)(sab + (swb1 ^ ((unsigned)i << 4)));
                uint4 av2 = make_uint4(0, 0, 0, 0);
                if (v2) av2 = *(const uint4*)(sab + (swb2 ^ ((unsigned)i << 4)));
                ull d1[4] = {h2f2(av1.x), h2f2(av1.y), h2f2(av1.z), h2f2(av1.w)};
                ull d2[4] = {h2f2(av2.x), h2f2(av2.y), h2f2(av2.z), h2f2(av2.w)};
#pragma unroll
                for (int h = 0; h < 4; h++) {
                    ulonglong2 wA = *(const ulonglong2*)(sw + h * 64 + i * 8);
                    ulonglong2 wB = *(const ulonglong2*)(sw + h * 64 + i * 8 + 4);
                    a1[h] = fma2(d1[0], wA.x, a1[h]);
                    a1[h] = fma2(d1[1], wA.y, a1[h]);
                    a1[h] = fma2(d1[2], wB.x, a1[h]);
                    a1[h] = fma2(d1[3], wB.y, a1[h]);
                    a2[h] = fma2(d2[0], wA.x, a2[h]);
                    a2[h] = fma2(d2[1], wA.y, a2[h]);
                    a2[h] = fma2(d2[2], wB.x, a2[h]);
                    a2[h] = fma2(d2[3], wB.y, a2[h]);
                }
            }
#pragma unroll
            for (int h = 0; h < 4; h++) {
                float2 f1 = unpack2(a1[h]); s1[h] = f1.x + f1.y;
                if (v2) { float2 f2 = unpack2(a2[h]); s2[h] = f2.x + f2.y; }
            }
        }

        // block max per head
        float mx[4];
#pragma unroll
        for (int h = 0; h < 4; h++) mx[h] = fmaxf(s1[h], s2[h]);
#pragma unroll
        for (int o = 16; o; o >>= 1)
#pragma unroll
            for (int h = 0; h < 4; h++)
                mx[h] = fmaxf(mx[h], __shfl_xor_sync(0xffffffffu, mx[h], o));
        if (lane == 0) {
#pragma unroll
            for (int h = 0; h < 4; h++) redm[wid * 4 + h] = mx[h];
        }
        __syncthreads();
        float mm[4];
#pragma unroll
        for (int h = 0; h < 4; h++)
            mm[h] = fmaxf(fmaxf(redm[h], redm[4 + h]),
                          fmaxf(redm[8 + h], redm[12 + h]));

        // p = exp(s - m), block sum per head, store p fp16
        float p1[4], p2[4], sm[4];
#pragma unroll
        for (int h = 0; h < 4; h++) {
            p1[h] = v1 ? __expf(s1[h] - mm[h]) : 0.f;
            p2[h] = v2 ? __expf(s2[h] - mm[h]) : 0.f;
            sm[h] = p1[h] + p2[h];
        }
#pragma unroll
        for (int o = 16; o; o >>= 1)
#pragma unroll
            for (int h = 0; h < 4; h++)
                sm[h] += __shfl_xor_sync(0xffffffffu, sm[h], o);
        if (lane == 0) {
#pragma unroll
            for (int h = 0; h < 4; h++) reds[wid * 4 + h] = sm[h];
        }
        if (v1) {
            ph0[sk1] = __floats2half2_rn(p1[0], p1[1]);
            ph1[sk1] = __floats2half2_rn(p1[2], p1[3]);
        }
        if (v2) {
            ph0[sk2] = __floats2half2_rn(p2[0], p2[1]);
            ph1[sk2] = __floats2half2_rn(p2[2], p2[3]);
        }
    }
    __syncthreads();

    if (t < 4) {
        float s = reds[t] + reds[4 + t] + reds[8 + t] + reds[12 + t];
        sinv[t] = 1.f / s;
    }

    // ---- Phase D: ctx partials. 128 threads = 16 sk-groups x 8 dim-octets.
    ull acc[16];
    {
        int sg = t >> 3, c8 = t & 7;
#pragma unroll
        for (int v = 0; v < 16; v++) acc[v] = 0ull;
        int chunk = (nsk + 15) >> 4;
        int sk0 = sg * chunk;
        int sk1e = sk0 + chunk; if (sk1e > nsk) sk1e = nsk;
        for (int sk = sk0; sk < sk1e; sk++) {
            unsigned off = (unsigned)(sk * 128) |
                           ((((unsigned)sk & 7u) ^ (unsigned)c8) << 4);
            uint4 av = *(const uint4*)(sab + off);
            ull d0 = h2f2(av.x), d1 = h2f2(av.y), d2 = h2f2(av.z), d3 = h2f2(av.w);
            float2 p01 = __half22float2(ph0[sk]);
            float2 p23 = __half22float2(ph1[sk]);
            ull ph0p = pack2(p01.x, p01.x), ph1p = pack2(p01.y, p01.y);
            ull ph2p = pack2(p23.x, p23.x), ph3p = pack2(p23.y, p23.y);
            acc[0]  = fma2(ph0p, d0, acc[0]);  acc[1]  = fma2(ph0p, d1, acc[1]);
            acc[2]  = fma2(ph0p, d2, acc[2]);  acc[3]  = fma2(ph0p, d3, acc[3]);
            acc[4]  = fma2(ph1p, d0, acc[4]);  acc[5]  = fma2(ph1p, d1, acc[5]);
            acc[6]  = fma2(ph1p, d2, acc[6]);  acc[7]  = fma2(ph1p, d3, acc[7]);
            acc[8]  = fma2(ph2p, d0, acc[8]);  acc[9]  = fma2(ph2p, d1, acc[9]);
            acc[10] = fma2(ph2p, d2, acc[10]); acc[11] = fma2(ph2p, d3, acc[11]);
            acc[12] = fma2(ph3p, d0, acc[12]); acc[13] = fma2(ph3p, d1, acc[13]);
            acc[14] = fma2(ph3p, d2, acc[14]); acc[15] = fma2(ph3p, d3, acc[15]);
        }
#pragma unroll
        for (int v = 0; v < 16; v++) {
            acc[v] = add2(acc[v], __shfl_xor_sync(0xffffffffu, acc[v], 8));
            acc[v] = add2(acc[v], __shfl_xor_sync(0xffffffffu, acc[v], 16));
        }
    }
    __syncthreads();   // tile reads complete; alias partials over tile

    if ((t & 24) == 0) {
        int w = t >> 5, c8 = t & 7;
        ull* pw = (ull*)partf + w * 128 + c8 * 4;
#pragma unroll
        for (int h = 0; h < 4; h++)
#pragma unroll
            for (int p = 0; p < 4; p++)
                pw[h * 32 + p] = acc[h * 4 + p];
    }
    __syncthreads();

    // ---- Phase E: combine partials -> normalized ctx into sw
    {
        float r0 = partf[t]       + partf[256 + t]       + partf[512 + t]       + partf[768 + t];
        float r1 = partf[t + 128] + partf[256 + t + 128] + partf[512 + t + 128] + partf[768 + t + 128];
        sw[t]       = r0 * sinv[t >> 6];
        sw[t + 128] = r1 * sinv[(t + 128) >> 6];
    }
    __syncthreads();

    // ---- Phase F: out[c] = sum_a ctx[h(c)*64+a] * V[a][c]
    if (t < 64) {
        int c = t, h = t >> 4;
        const ull* cx = (const ull*)(sw + h * 64);
        ull acc2 = 0ull;
#pragma unroll 8
        for (int a = 0; a < 32; a++) {
            float v0 = __ldg(V + (size_t)(2 * a) * 64 + c);
            float v1 = __ldg(V + (size_t)(2 * a + 1) * 64 + c);
            acc2 = fma2(cx[a], pack2(v0, v1), acc2);
        }
        float2 f = unpack2(acc2);
        out[(size_t)b * 64 + c] = f.x + f.y;
    }
}

// ---------------------------------------------------------------------------
extern "C" void kernel_launch(void* const* d_in, const int* in_sizes, int n_in,
                              void* d_out, int out_size) {
    const float* query = (const float*)d_in[0];   // [B,1,64]
    const float* act   = (const float*)d_in[1];   // [B,SK,64]
    const float* Q     = (const float*)d_in[2];   // [64,64]
    const float* K     = (const float*)d_in[3];   // [64,64]
    const float* V     = (const float*)d_in[4];   // [64,64]
    float* out = (float*)d_out;

    int B   = in_sizes[0] / 64;
    int nsk = in_sizes[1] / (B * 64);
    if (nsk > TCAP) nsk = TCAP;

    cudaFuncSetAttribute(k2_fused, cudaFuncAttributeMaxDynamicSharedMemorySize, SMEM_BYTES);

    k1_w<<<(B + 63) / 64, 256>>>(query, Q, K, B);

    cudaLaunchConfig_t cfg = {};
    cfg.gridDim = dim3((unsigned)B, 1, 1);
    cfg.blockDim = dim3(128, 1, 1);
    cfg.dynamicSmemBytes = SMEM_BYTES;
    cfg.stream = 0;
    cudaLaunchAttribute attrs[1];
    attrs[0].id = cudaLaunchAttributeProgrammaticStreamSerialization;
    attrs[0].val.programmaticStreamSerializationAllowed = 1;
    cfg.attrs = attrs;
    cfg.numAttrs = 1;
    cudaLaunchKernelEx(&cfg, k2_fused, act, V, out, nsk);
}

// round 17
// speedup vs baseline: 1.0485x; 1.0133x over previous
#include <cuda_runtime.h>
#include <cuda_fp16.h>

#define TCAP  200
#define MDIM  256
#define BMAX  8192

__device__ float g_W[(size_t)BMAX * MDIM];   // 8 MB scratch

typedef unsigned long long ull;

// ---- packed fp32x2 helpers ----
__device__ __forceinline__ ull fma2(ull a, ull b, ull c) {
    ull d;
    asm("fma.rn.f32x2 %0, %1, %2, %3;" : "=l"(d) : "l"(a), "l"(b), "l"(c));
    return d;
}
__device__ __forceinline__ ull add2(ull a, ull b) {
    ull d;
    asm("add.rn.f32x2 %0, %1, %2;" : "=l"(d) : "l"(a), "l"(b));
    return d;
}
__device__ __forceinline__ ull pack2(float x, float y) {
    ull r;
    asm("mov.b64 %0, {%1, %2};" : "=l"(r) : "f"(x), "f"(y));
    return r;
}
__device__ __forceinline__ float2 unpack2(ull a) {
    float2 f;
    asm("mov.b64 {%0, %1}, %2;" : "=f"(f.x), "=f"(f.y) : "l"(a));
    return f;
}
__device__ __forceinline__ ull h2f2(unsigned h) {
    ull r;
    asm("{\n\t.reg .b16 lo, hi;\n\t.reg .f32 flo, fhi;\n\t"
        "mov.b32 {lo, hi}, %1;\n\t"
        "cvt.f32.f16 flo, lo;\n\tcvt.f32.f16 fhi, hi;\n\t"
        "mov.b64 %0, {flo, fhi};\n\t}" : "=l"(r) : "r"(h));
    return r;
}

// ---------------------------------------------------------------------------
// K1 (fat, PDL trigger): 64 batches/CTA, 128 CTAs — unchanged (proven).
// ---------------------------------------------------------------------------
__global__ __launch_bounds__(256) void k1_w(const float* __restrict__ query,
                                            const float* __restrict__ Qm,
                                            const float* __restrict__ Km, int B) {
    cudaTriggerProgrammaticLaunchCompletion();

    __shared__ float sQ[64 * 64];
    __shared__ float qs[64 * 64];
    __shared__ float sK[64 * 68];
    __shared__ float qp[64 * 64];
    int b0 = blockIdx.x * 64, t = threadIdx.x;

    for (int idx = t; idx < 4096; idx += 256) {
        sQ[idx] = Qm[idx];
        sK[(idx >> 6) * 68 + (idx & 63)] = Km[idx];
        int bb = idx >> 6;
        qs[idx] = (b0 + bb < B) ? query[(size_t)(b0 + bb) * 64 + (idx & 63)] : 0.f;
    }
    __syncthreads();

    {
        int bg = t >> 6, c = t & 63;
        float acc[16];
#pragma unroll
        for (int b = 0; b < 16; b++) acc[b] = 0.f;
#pragma unroll 4
        for (int i4 = 0; i4 < 16; i4++) {
            float q0 = sQ[(i4 * 4 + 0) * 64 + c];
            float q1 = sQ[(i4 * 4 + 1) * 64 + c];
            float q2 = sQ[(i4 * 4 + 2) * 64 + c];
            float q3 = sQ[(i4 * 4 + 3) * 64 + c];
#pragma unroll
            for (int b = 0; b < 16; b++) {
                float4 v = *(const float4*)(qs + (bg * 16 + b) * 64 + i4 * 4);
                acc[b] += v.x * q0 + v.y * q1 + v.z * q2 + v.w * q3;
            }
        }
#pragma unroll
        for (int b = 0; b < 16; b++)
            qp[(bg * 16 + b) * 64 + c] = acc[b];
    }
    __syncthreads();

    {
        int h = t >> 6, a = t & 63;
        const float4* K4 = (const float4*)(sK + a * 68 + h * 16);
        float4 k0 = K4[0], k1 = K4[1], k2 = K4[2], k3 = K4[3];
        int bmax = B - b0; if (bmax > 64) bmax = 64;
        for (int b = 0; b < bmax; b++) {
            const float4* q4 = (const float4*)(qp + b * 64 + h * 16);
            float4 qa = q4[0], qb = q4[1], qc = q4[2], qd = q4[3];
            float wv = qa.x * k0.x + qa.y * k0.y + qa.z * k0.z + qa.w * k0.w
                     + qb.x * k1.x + qb.y * k1.y + qb.z * k1.z + qb.w * k1.w
                     + qc.x * k2.x + qc.y * k2.y + qc.z * k2.z + qc.w * k2.w
                     + qd.x * k3.x + qd.y * k3.y + qd.z * k3.z + qd.w * k3.w;
            g_W[(size_t)(b0 + b) * MDIM + t] = 0.125f * wv;
        }
    }
}

// ---------------------------------------------------------------------------
// K2: R16 attention + packed-p (one ull per sk) + unrolled Phase D.
// ---------------------------------------------------------------------------
#define SA_BYTES   (TCAP * 128)               // 25600: fp16 swizzled tile (aliased later)
#define SW_OFF     SA_BYTES                   // 1024: W row, later ctx
#define PH_OFF     (SW_OFF + 1024)            // 1600: p as ull[200] (4 halves each)
#define RED_OFF    (PH_OFF + 1600)            // 128: redmax[16] + redsum[16]
#define SINV_OFF   (RED_OFF + 128)            // 16
#define SMEM_BYTES (SINV_OFF + 16)            // 28368

extern __shared__ char s_raw[];

__global__ __launch_bounds__(128, 8) void k2_fused(const float* __restrict__ act,
                                                   const float* __restrict__ V,
                                                   float* __restrict__ out, int nsk) {
    char*  sab   = s_raw;
    float* sw    = (float*)(s_raw + SW_OFF);
    ull*   php   = (ull*)(s_raw + PH_OFF);
    float* redm  = (float*)(s_raw + RED_OFF);
    float* reds  = (float*)(s_raw + RED_OFF + 64);
    float* sinv  = (float*)(s_raw + SINV_OFF);
    float* partf = (float*)s_raw;             // aliases tile after ctx phase

    int b = blockIdx.x;
    int t = threadIdx.x;
    int wid = t >> 5, lane = t & 31;

    // ---- Phase A: action tile -> fp16, XOR-swizzled (coalesced loads)
    {
        const float4* ga = (const float4*)(act + (size_t)b * nsk * 64);
        int nq = nsk * 16;                    // float4 count (3200)
#pragma unroll 4
        for (int j = t; j < nq; j += 128) {
            float4 f = ga[j];
            __half2 h0 = __floats2half2_rn(f.x, f.y);
            __half2 h1 = __floats2half2_rn(f.z, f.w);
            uint2 pk;
            pk.x = *(const unsigned*)&h0;
            pk.y = *(const unsigned*)&h1;
            unsigned g = (unsigned)j >> 1, hs = (unsigned)j & 1u;
            unsigned off = ((g << 4) ^ (((g >> 3) & 7u) << 4)) + (hs << 3);
            *(uint2*)(sab + off) = pk;
        }
    }

    // ---- Wait for k1 (g_W), then load W row
    cudaGridDependencySynchronize();
    sw[t]       = g_W[(size_t)b * MDIM + t];
    sw[t + 128] = g_W[(size_t)b * MDIM + t + 128];
    __syncthreads();

    // ---- Phase B+C fused: scores in regs, block softmax, p packed fp16
    {
        int sk1 = t, sk2 = t + 128;
        bool v1 = sk1 < nsk, v2 = sk2 < nsk;
        float s1[4] = {-1e30f, -1e30f, -1e30f, -1e30f};
        float s2[4] = {-1e30f, -1e30f, -1e30f, -1e30f};
        if (v1) {
            unsigned swb1 = (unsigned)(sk1 * 128) | (((unsigned)sk1 & 7u) << 4);
            unsigned swb2 = (unsigned)(sk2 * 128) | (((unsigned)sk2 & 7u) << 4);
            ull a1[4] = {0, 0, 0, 0}, a2[4] = {0, 0, 0, 0};
#pragma unroll
            for (int i = 0; i < 8; i++) {
                uint4 av1 = *(const uint4*)(sab + (swb1 ^ ((unsigned)i << 4)));
                uint4 av2 = make_uint4(0, 0, 0, 0);
                if (v2) av2 = *(const uint4*)(sab + (swb2 ^ ((unsigned)i << 4)));
                ull d1[4] = {h2f2(av1.x), h2f2(av1.y), h2f2(av1.z), h2f2(av1.w)};
                ull d2[4] = {h2f2(av2.x), h2f2(av2.y), h2f2(av2.z), h2f2(av2.w)};
#pragma unroll
                for (int h = 0; h < 4; h++) {
                    ulonglong2 wA = *(const ulonglong2*)(sw + h * 64 + i * 8);
                    ulonglong2 wB = *(const ulonglong2*)(sw + h * 64 + i * 8 + 4);
                    a1[h] = fma2(d1[0], wA.x, a1[h]);
                    a1[h] = fma2(d1[1], wA.y, a1[h]);
                    a1[h] = fma2(d1[2], wB.x, a1[h]);
                    a1[h] = fma2(d1[3], wB.y, a1[h]);
                    a2[h] = fma2(d2[0], wA.x, a2[h]);
                    a2[h] = fma2(d2[1], wA.y, a2[h]);
                    a2[h] = fma2(d2[2], wB.x, a2[h]);
                    a2[h] = fma2(d2[3], wB.y, a2[h]);
                }
            }
#pragma unroll
            for (int h = 0; h < 4; h++) {
                float2 f1 = unpack2(a1[h]); s1[h] = f1.x + f1.y;
                if (v2) { float2 f2 = unpack2(a2[h]); s2[h] = f2.x + f2.y; }
            }
        }

        // block max per head
        float mx[4];
#pragma unroll
        for (int h = 0; h < 4; h++) mx[h] = fmaxf(s1[h], s2[h]);
#pragma unroll
        for (int o = 16; o; o >>= 1)
#pragma unroll
            for (int h = 0; h < 4; h++)
                mx[h] = fmaxf(mx[h], __shfl_xor_sync(0xffffffffu, mx[h], o));
        if (lane == 0) {
#pragma unroll
            for (int h = 0; h < 4; h++) redm[wid * 4 + h] = mx[h];
        }
        __syncthreads();
        float mm[4];
#pragma unroll
        for (int h = 0; h < 4; h++)
            mm[h] = fmaxf(fmaxf(redm[h], redm[4 + h]),
                          fmaxf(redm[8 + h], redm[12 + h]));

        // p = exp(s - m), block sum per head, store p packed fp16 (one ull)
        float p1[4], p2[4], sm[4];
#pragma unroll
        for (int h = 0; h < 4; h++) {
            p1[h] = v1 ? __expf(s1[h] - mm[h]) : 0.f;
            p2[h] = v2 ? __expf(s2[h] - mm[h]) : 0.f;
            sm[h] = p1[h] + p2[h];
        }
#pragma unroll
        for (int o = 16; o; o >>= 1)
#pragma unroll
            for (int h = 0; h < 4; h++)
                sm[h] += __shfl_xor_sync(0xffffffffu, sm[h], o);
        if (lane == 0) {
#pragma unroll
            for (int h = 0; h < 4; h++) reds[wid * 4 + h] = sm[h];
        }
        if (v1) {
            __half2 ha = __floats2half2_rn(p1[0], p1[1]);
            __half2 hb = __floats2half2_rn(p1[2], p1[3]);
            php[sk1] = ((ull)(*(const unsigned*)&hb) << 32) | (*(const unsigned*)&ha);
        }
        if (v2) {
            __half2 ha = __floats2half2_rn(p2[0], p2[1]);
            __half2 hb = __floats2half2_rn(p2[2], p2[3]);
            php[sk2] = ((ull)(*(const unsigned*)&hb) << 32) | (*(const unsigned*)&ha);
        }
    }
    __syncthreads();

    if (t < 4) {
        float s = reds[t] + reds[4 + t] + reds[8 + t] + reds[12 + t];
        sinv[t] = 1.f / s;
    }

    // ---- Phase D: ctx partials. 128 threads = 16 sk-groups x 8 dim-octets.
    ull acc[16];
    {
        int sg = t >> 3, c8 = t & 7;
#pragma unroll
        for (int v = 0; v < 16; v++) acc[v] = 0ull;
        int chunk = (nsk + 15) >> 4;
        int sk0 = sg * chunk;
        int sk1e = sk0 + chunk; if (sk1e > nsk) sk1e = nsk;
#pragma unroll 2
        for (int sk = sk0; sk < sk1e; sk++) {
            unsigned off = (unsigned)(sk * 128) |
                           ((((unsigned)sk & 7u) ^ (unsigned)c8) << 4);
            uint4 av = *(const uint4*)(sab + off);
            ull pv = php[sk];
            unsigned plo = (unsigned)pv, phi = (unsigned)(pv >> 32);
            ull d0 = h2f2(av.x), d1 = h2f2(av.y), d2 = h2f2(av.z), d3 = h2f2(av.w);
            float2 p01 = __half22float2(*(const __half2*)&plo);
            float2 p23 = __half22float2(*(const __half2*)&phi);
            ull ph0p = pack2(p01.x, p01.x), ph1p = pack2(p01.y, p01.y);
            ull ph2p = pack2(p23.x, p23.x), ph3p = pack2(p23.y, p23.y);
            acc[0]  = fma2(ph0p, d0, acc[0]);  acc[1]  = fma2(ph0p, d1, acc[1]);
            acc[2]  = fma2(ph0p, d2, acc[2]);  acc[3]  = fma2(ph0p, d3, acc[3]);
            acc[4]  = fma2(ph1p, d0, acc[4]);  acc[5]  = fma2(ph1p, d1, acc[5]);
            acc[6]  = fma2(ph1p, d2, acc[6]);  acc[7]  = fma2(ph1p, d3, acc[7]);
            acc[8]  = fma2(ph2p, d0, acc[8]);  acc[9]  = fma2(ph2p, d1, acc[9]);
            acc[10] = fma2(ph2p, d2, acc[10]); acc[11] = fma2(ph2p, d3, acc[11]);
            acc[12] = fma2(ph3p, d0, acc[12]); acc[13] = fma2(ph3p, d1, acc[13]);
            acc[14] = fma2(ph3p, d2, acc[14]); acc[15] = fma2(ph3p, d3, acc[15]);
        }
#pragma unroll
        for (int v = 0; v < 16; v++) {
            acc[v] = add2(acc[v], __shfl_xor_sync(0xffffffffu, acc[v], 8));
            acc[v] = add2(acc[v], __shfl_xor_sync(0xffffffffu, acc[v], 16));
        }
    }
    __syncthreads();   // tile reads complete; alias partials over tile

    if ((t & 24) == 0) {
        int w = t >> 5, c8 = t & 7;
        ull* pw = (ull*)partf + w * 128 + c8 * 4;
#pragma unroll
        for (int h = 0; h < 4; h++)
#pragma unroll
            for (int p = 0; p < 4; p++)
                pw[h * 32 + p] = acc[h * 4 + p];
    }
    __syncthreads();

    // ---- Phase E: combine partials -> normalized ctx into sw
    {
        float r0 = partf[t]       + partf[256 + t]       + partf[512 + t]       + partf[768 + t];
        float r1 = partf[t + 128] + partf[256 + t + 128] + partf[512 + t + 128] + partf[768 + t + 128];
        sw[t]       = r0 * sinv[t >> 6];
        sw[t + 128] = r1 * sinv[(t + 128) >> 6];
    }
    __syncthreads();

    // ---- Phase F: out[c] = sum_a ctx[h(c)*64+a] * V[a][c]
    if (t < 64) {
        int c = t, h = t >> 4;
        const ull* cx = (const ull*)(sw + h * 64);
        ull acc2 = 0ull;
#pragma unroll 8
        for (int a = 0; a < 32; a++) {
            float v0 = __ldg(V + (size_t)(2 * a) * 64 + c);
            float v1 = __ldg(V + (size_t)(2 * a + 1) * 64 + c);
            acc2 = fma2(cx[a], pack2(v0, v1), acc2);
        }
        float2 f = unpack2(acc2);
        out[(size_t)b * 64 + c] = f.x + f.y;
    }
}

// ---------------------------------------------------------------------------
extern "C" void kernel_launch(void* const* d_in, const int* in_sizes, int n_in,
                              void* d_out, int out_size) {
    const float* query = (const float*)d_in[0];   // [B,1,64]
    const float* act   = (const float*)d_in[1];   // [B,SK,64]
    const float* Q     = (const float*)d_in[2];   // [64,64]
    const float* K     = (const float*)d_in[3];   // [64,64]
    const float* V     = (const float*)d_in[4];   // [64,64]
    float* out = (float*)d_out;

    int B   = in_sizes[0] / 64;
    int nsk = in_sizes[1] / (B * 64);
    if (nsk > TCAP) nsk = TCAP;

    cudaFuncSetAttribute(k2_fused, cudaFuncAttributeMaxDynamicSharedMemorySize, SMEM_BYTES);

    k1_w<<<(B + 63) / 64, 256>>>(query, Q, K, B);

    cudaLaunchConfig_t cfg = {};
    cfg.gridDim = dim3((unsigned)B, 1, 1);
    cfg.blockDim = dim3(128, 1, 1);
    cfg.dynamicSmemBytes = SMEM_BYTES;
    cfg.stream = 0;
    cudaLaunchAttribute attrs[1];
    attrs[0].id = cudaLaunchAttributeProgrammaticStreamSerialization;
    attrs[0].val.programmaticStreamSerializationAllowed = 1;
    cfg.attrs = attrs;
    cfg.numAttrs = 1;
    cudaLaunchKernelEx(&cfg, k2_fused, act, V, out, nsk);
}